// round 1
// baseline (speedup 1.0000x reference)
#include <cuda_runtime.h>

// Occupancy connectivity loss over a 385^3 fp32 grid:
//   sum over the 3 forward axis-aligned neighbor differences of |occ_i - occ_j|.
// Flat layout (C order): f = x*385^2 + y*385 + z.
//   z-neighbor: f+1      (valid if z != 384)
//   y-neighbor: f+385    (valid if y != 384)
//   x-neighbor: f+148225 (valid if x != 384)

#define NTOT  57066625u   // 385^3
#define PLANE 148225u     // 385^2
#define ROW   385u

__device__ double g_part[256];

__global__ void occ_zero_kernel() {
    g_part[threadIdx.x] = 0.0;
}

__global__ void __launch_bounds__(256) occ_main_kernel(const float* __restrict__ occ) {
    unsigned tid = blockIdx.x * blockDim.x + threadIdx.x;
    unsigned f0  = tid << 2;   // 4 elements per thread, 16B-aligned
    float s = 0.0f;

    if (f0 < NTOT) {
        // coordinates of element f0 (one roll-over max across the 4 elements)
        unsigned q = f0 / ROW;
        unsigned z = f0 - q * ROW;
        unsigned x = q / ROW;
        unsigned y = q - x * ROW;

        if (f0 + PLANE + 4u <= NTOT) {
            // ---- fast path: all neighbor loads in-bounds, vectorized ----
            float4 c  = *reinterpret_cast<const float4*>(occ + f0);
            float  c4 = __ldg(occ + f0 + 4u);
            // y-neighbors f0+385..f0+388: aligned float4 at f0+384 + scalar at f0+388
            float4 ay = *reinterpret_cast<const float4*>(occ + f0 + (ROW - 1u));
            float  y4 = __ldg(occ + f0 + (ROW + 3u));
            // x-neighbors f0+148225..f0+148228: aligned float4 at f0+148224 + scalar
            float4 ax = *reinterpret_cast<const float4*>(occ + f0 + (PLANE - 1u));
            float  x4 = __ldg(occ + f0 + (PLANE + 3u));

            float cur[4] = {c.x,  c.y,  c.z,  c.w};
            float zn[4]  = {c.y,  c.z,  c.w,  c4};
            float yn[4]  = {ay.y, ay.z, ay.w, y4};
            float xn[4]  = {ax.y, ax.z, ax.w, x4};

            #pragma unroll
            for (int k = 0; k < 4; ++k) {
                if (z != 384u) s += fabsf(zn[k] - cur[k]);
                if (y != 384u) s += fabsf(yn[k] - cur[k]);
                if (x != 384u) s += fabsf(xn[k] - cur[k]);
                if (++z == 385u) { z = 0u; if (++y == 385u) { y = 0u; ++x; } }
            }
        } else {
            // ---- slow tail path (last ~37K threads): fully guarded scalars ----
            #pragma unroll
            for (int k = 0; k < 4; ++k) {
                unsigned f = f0 + (unsigned)k;
                if (f < NTOT) {
                    float cv = __ldg(occ + f);
                    if (z != 384u) s += fabsf(__ldg(occ + f + 1u)    - cv);
                    if (y != 384u) s += fabsf(__ldg(occ + f + ROW)   - cv);
                    if (x != 384u) s += fabsf(__ldg(occ + f + PLANE) - cv);
                }
                if (++z == 385u) { z = 0u; if (++y == 385u) { y = 0u; ++x; } }
            }
        }
    }

    // ---- block reduction (fp32 within block is plenty accurate) ----
    #pragma unroll
    for (int o = 16; o > 0; o >>= 1)
        s += __shfl_down_sync(0xffffffffu, s, o);

    __shared__ float wsum[8];
    unsigned lane = threadIdx.x & 31u;
    unsigned wid  = threadIdx.x >> 5;
    if (lane == 0u) wsum[wid] = s;
    __syncthreads();
    if (wid == 0u) {
        float v = (lane < 8u) ? wsum[lane] : 0.0f;
        #pragma unroll
        for (int o = 4; o > 0; o >>= 1)
            v += __shfl_down_sync(0xffffffffu, v, o);
        if (lane == 0u)
            atomicAdd(&g_part[blockIdx.x & 255u], (double)v);
    }
}

__global__ void occ_finalize_kernel(float* __restrict__ out) {
    __shared__ double sm[256];
    sm[threadIdx.x] = g_part[threadIdx.x];
    __syncthreads();
    #pragma unroll
    for (int st = 128; st > 0; st >>= 1) {
        if ((int)threadIdx.x < st) sm[threadIdx.x] += sm[threadIdx.x + st];
        __syncthreads();
    }
    if (threadIdx.x == 0) out[0] = (float)sm[0];
}

extern "C" void kernel_launch(void* const* d_in, const int* in_sizes, int n_in,
                              void* d_out, int out_size) {
    const float* occ = (const float*)d_in[0];
    float* out = (float*)d_out;

    const unsigned n_threads = (NTOT + 3u) / 4u;          // 14,266,657
    const unsigned n_blocks  = (n_threads + 255u) / 256u; // 55,730

    occ_zero_kernel<<<1, 256>>>();
    occ_main_kernel<<<n_blocks, 256>>>(occ);
    occ_finalize_kernel<<<1, 256>>>(out);
}